// round 13
// baseline (speedup 1.0000x reference)
#include <cuda_runtime.h>
#include <cuda_fp16.h>
#include <cstdint>

#define ND 128
#define NQ 128
#define LD 128
#define LQ 32
#define EDIM 128

// f16 staging (device globals: no allocation allowed)
__device__ __half g_doc[ND * LD * EDIM];      // [d][t][e]
__device__ __half g_qT[NQ * LQ * EDIM];       // [q][l][e]

// ---------------------------------------------------------------------------
// Merged conversion kernel: blocks [0,2048) convert doc, [2048,2176) convert q
// ---------------------------------------------------------------------------
__global__ void conv_all_kernel(const float* __restrict__ doc, const float* __restrict__ q) {
    __shared__ float s[128 * 33];
    if (blockIdx.x < 2048) {
        int i = blockIdx.x * 256 + threadIdx.x;    // 524288 threads, 1 float4 each
        float4 v = reinterpret_cast<const float4*>(doc)[i];
        __half2 lo = __floats2half2_rn(v.x, v.y);
        __half2 hi = __floats2half2_rn(v.z, v.w);
        uint2 o;
        o.x = *reinterpret_cast<uint32_t*>(&lo);
        o.y = *reinterpret_cast<uint32_t*>(&hi);
        reinterpret_cast<uint2*>(g_doc)[i] = o;
    } else {
        // in[q][e][l] (e:128, l:32)  ->  g_qT[q][l][e]
        int qq = blockIdx.x - 2048;
        const float* src = q + qq * 4096;
        int tid = threadIdx.x;  // 256
        #pragma unroll
        for (int i = 0; i < 16; i++) {
            int idx = tid + i * 256;
            int e = idx >> 5, l = idx & 31;
            s[e * 33 + l] = src[idx];
        }
        __syncthreads();
        __half* dst = g_qT + qq * 4096;
        #pragma unroll
        for (int i = 0; i < 16; i++) {
            int idx = tid + i * 256;
            int l = idx >> 7, e = idx & 127;
            dst[idx] = __float2half_rn(s[e * 33 + l]);
        }
    }
}

// ---------------------------------------------------------------------------
// Primitives
// ---------------------------------------------------------------------------
__device__ __forceinline__ void mma16816_f16(uint32_t* c, const uint32_t* a, const uint32_t* b) {
    asm volatile(
        "mma.sync.aligned.m16n8k16.row.col.f16.f16.f16.f16 "
        "{%0,%1}, {%2,%3,%4,%5}, {%6,%7}, {%0,%1};\n"
        : "+r"(c[0]), "+r"(c[1])
        : "r"(a[0]), "r"(a[1]), "r"(a[2]), "r"(a[3]),
          "r"(b[0]), "r"(b[1]));
}

#define LDSM_X4(r0, r1, r2, r3, addr) \
    asm volatile("ldmatrix.sync.aligned.m8n8.x4.shared.b16 {%0,%1,%2,%3}, [%4];" \
                 : "=r"(r0), "=r"(r1), "=r"(r2), "=r"(r3) : "r"(addr))

__device__ __forceinline__ uint32_t smem_u32(const void* p) {
    uint32_t a;
    asm("{ .reg .u64 t; cvta.to.shared.u64 t, %1; cvt.u32.u64 %0, t; }" : "=r"(a) : "l"(p));
    return a;
}

#define CP16(saddr, gptr) \
    asm volatile("cp.async.cg.shared.global [%0], [%1], 16;" :: "r"(saddr), "l"(gptr))
#define CP_COMMIT() asm volatile("cp.async.commit_group;")
#define CP_WAIT(n)  asm volatile("cp.async.wait_group %0;" :: "n"(n))

// padded smem row: 136 f16 = 272 B (conflict-free LDSM, verified R4-R11)
#define ROWB 272
#define TILE_BYTES (128 * ROWB)                  // 34816
#define A_OFF(dd) ((dd) * TILE_BYTES)
#define B_OFF (2 * TILE_BYTES)
#define CM_OFF (3 * TILE_BYTES)                  // colmax [2][2][128] floats = 2048 B
#define SMEM_TOTAL (3 * TILE_BYTES + 2048)       // 106496 -> 2 CTAs/SM

// CTA: 256 threads = 8 warps in 2(doc) x 2(m) x 2(n); warp tile 64x64, f16 acc.
// Both docs computed concurrently by disjoint warp quads.
// Cold load split by k-half: compute k[0,64) while k[64,128) streams in.
__global__ void __launch_bounds__(256) maxsim_kernel(float* __restrict__ out) {
    extern __shared__ char smem[];
    float* colmax = reinterpret_cast<float*>(smem + CM_OFF);   // [doc][wm][128]

    const int dbase = blockIdx.x * 2;
    const int qg = blockIdx.y;
    const int tid = threadIdx.x;
    const int warp = tid >> 5;
    const int lane = tid & 31;
    const int wd = warp >> 2;         // doc within pair
    const int wm = (warp >> 1) & 1;   // m half
    const int wn = warp & 1;          // n half
    const int t4 = lane & 3;
    const int matid = lane >> 3;
    const int mrow = lane & 7;

    const uint32_t sbase = smem_u32(smem);

    // ---- async tile loads, split by k-half ----
    {
        const uint4* srcq  = reinterpret_cast<const uint4*>(g_qT + qg * 4 * LQ * EDIM);
        const uint4* srcd0 = reinterpret_cast<const uint4*>(g_doc + dbase * LD * EDIM);
        const uint4* srcd1 = reinterpret_cast<const uint4*>(g_doc + (dbase + 1) * LD * EDIM);
        // group 1: k columns [0,64)  (col16 0..7 of each 128-row tile)
        #pragma unroll
        for (int i = 0; i < 4; i++) {
            int idx = tid + i * 256;                 // 0..1023
            int row = idx >> 3, col = idx & 7;
            uint32_t soff = (uint32_t)(row * 17 + col) * 16;
            int gidx = row * 16 + col;
            CP16(sbase + B_OFF + soff, srcq + gidx);
            CP16(sbase + A_OFF(0) + soff, srcd0 + gidx);
            CP16(sbase + A_OFF(1) + soff, srcd1 + gidx);
        }
        CP_COMMIT();
        // group 2: k columns [64,128)  (col16 8..15)
        #pragma unroll
        for (int i = 0; i < 4; i++) {
            int idx = tid + i * 256;
            int row = idx >> 3, col = (idx & 7) + 8;
            uint32_t soff = (uint32_t)(row * 17 + col) * 16;
            int gidx = row * 16 + col;
            CP16(sbase + B_OFF + soff, srcq + gidx);
            CP16(sbase + A_OFF(0) + soff, srcd0 + gidx);
            CP16(sbase + A_OFF(1) + soff, srcd1 + gidx);
        }
        CP_COMMIT();
    }

    // LDSM per-lane offsets (verified mapping, 64x64 warp tile)
    uint32_t arow_off[4];
    #pragma unroll
    for (int mt = 0; mt < 4; mt++)
        arow_off[mt] = (uint32_t)((wm * 64 + mt * 16 + (matid & 1) * 8 + mrow) * ROWB
                                  + (matid >> 1) * 16);
    uint32_t brow_off[4];
    #pragma unroll
    for (int np = 0; np < 4; np++)
        brow_off[np] = (uint32_t)(B_OFF + (wn * 64 + np * 16 + (matid >> 1) * 8 + mrow) * ROWB
                                  + (matid & 1) * 16);

    CP_WAIT(1);                    // k-half 0 of all 3 tiles resident
    __syncthreads();

    const uint32_t sA = sbase + A_OFF(wd);

    uint32_t acc[4][8][2];
    #pragma unroll
    for (int mt = 0; mt < 4; mt++)
        #pragma unroll
        for (int nt = 0; nt < 8; nt++) {
            acc[mt][nt][0] = 0u;
            acc[mt][nt][1] = 0u;
        }

    // ---- k-half 0: k0 = 0,16,32,48 ----
    #pragma unroll
    for (int k0 = 0; k0 < 64; k0 += 16) {
        uint32_t a[4][4], b[8][2];
        #pragma unroll
        for (int mt = 0; mt < 4; mt++)
            LDSM_X4(a[mt][0], a[mt][1], a[mt][2], a[mt][3], sA + arow_off[mt] + k0 * 2);
        #pragma unroll
        for (int np = 0; np < 4; np++) {
            uint32_t t0, t1, t2, t3;
            LDSM_X4(t0, t1, t2, t3, sbase + brow_off[np] + k0 * 2);
            b[2 * np][0] = t0; b[2 * np][1] = t1;
            b[2 * np + 1][0] = t2; b[2 * np + 1][1] = t3;
        }
        #pragma unroll
        for (int mt = 0; mt < 4; mt++)
            #pragma unroll
            for (int nt = 0; nt < 8; nt++)
                mma16816_f16(acc[mt][nt], a[mt], b[nt]);
    }

    CP_WAIT(0);                    // k-half 1 resident
    __syncthreads();

    // ---- k-half 1: k0 = 64,80,96,112 ----
    #pragma unroll
    for (int k0 = 64; k0 < 128; k0 += 16) {
        uint32_t a[4][4], b[8][2];
        #pragma unroll
        for (int mt = 0; mt < 4; mt++)
            LDSM_X4(a[mt][0], a[mt][1], a[mt][2], a[mt][3], sA + arow_off[mt] + k0 * 2);
        #pragma unroll
        for (int np = 0; np < 4; np++) {
            uint32_t t0, t1, t2, t3;
            LDSM_X4(t0, t1, t2, t3, sbase + brow_off[np] + k0 * 2);
            b[2 * np][0] = t0; b[2 * np][1] = t1;
            b[2 * np + 1][0] = t2; b[2 * np + 1][1] = t3;
        }
        #pragma unroll
        for (int mt = 0; mt < 4; mt++)
            #pragma unroll
            for (int nt = 0; nt < 8; nt++)
                mma16816_f16(acc[mt][nt], a[mt], b[nt]);
    }

    // ---- warp max over its 64 doc-token rows (packed f16x2 per col pair) ----
    #pragma unroll
    for (int nt = 0; nt < 8; nt++) {
        __half2 hm = __hmax2(*reinterpret_cast<__half2*>(&acc[0][nt][0]),
                             *reinterpret_cast<__half2*>(&acc[0][nt][1]));
        #pragma unroll
        for (int mt = 1; mt < 4; mt++) {
            hm = __hmax2(hm, *reinterpret_cast<__half2*>(&acc[mt][nt][0]));
            hm = __hmax2(hm, *reinterpret_cast<__half2*>(&acc[mt][nt][1]));
        }
        #pragma unroll
        for (int off = 4; off < 32; off <<= 1) {
            uint32_t u = __shfl_xor_sync(0xffffffffu, *reinterpret_cast<uint32_t*>(&hm), off);
            hm = __hmax2(hm, *reinterpret_cast<__half2*>(&u));
        }
        if (lane < 4) {   // lane == t4
            float2 f = __half22float2(hm);
            colmax[wd * 256 + wm * 128 + wn * 64 + nt * 8 + 2 * t4]     = f.x;
            colmax[wd * 256 + wm * 128 + wn * 64 + nt * 8 + 2 * t4 + 1] = f.y;
        }
    }
    __syncthreads();

    // ---- cross-warp max over t, then f32 sum over l per query ----
    {
        const int col = tid & 127;          // ql index within group; tid>>7 = doc
        const int dd = tid >> 7;
        float v = fmaxf(colmax[dd * 256 + col], colmax[dd * 256 + 128 + col]);
        #pragma unroll
        for (int off = 16; off; off >>= 1)
            v += __shfl_xor_sync(0xffffffffu, v, off);
        if (lane == 0)
            out[(qg * 4 + (col >> 5)) * ND + dbase + dd] = v;
    }
}

// ---------------------------------------------------------------------------
extern "C" void kernel_launch(void* const* d_in, const int* in_sizes, int n_in,
                              void* d_out, int out_size) {
    const float* doc   = (const float*)d_in[0];   // [128,128,128]
    const float* query = (const float*)d_in[1];   // [128,128,32]
    float* out = (float*)d_out;                   // [128,128]

    cudaFuncSetAttribute(maxsim_kernel, cudaFuncAttributeMaxDynamicSharedMemorySize, SMEM_TOTAL);

    conv_all_kernel<<<2176, 256>>>(doc, query);

    dim3 grid(ND / 2, LQ);   // 64 doc-pairs x 32 query groups
    maxsim_kernel<<<grid, 256, SMEM_TOTAL>>>(out);
}

// round 14
// speedup vs baseline: 1.5274x; 1.5274x over previous
#include <cuda_runtime.h>
#include <cuda_fp16.h>
#include <cstdint>

#define ND 128
#define NQ 128
#define LD 128
#define LQ 32
#define EDIM 128

// f16 staging (device globals: no allocation allowed)
__device__ __half g_doc[ND * LD * EDIM];      // [d][t][e]
__device__ __half g_qT[NQ * LQ * EDIM];       // [q][l][e]

// ---------------------------------------------------------------------------
// Merged conversion kernel: blocks [0,2048) convert doc, [2048,2176) convert q
// (R11-measured: 3.55 us total)
// ---------------------------------------------------------------------------
__global__ void conv_all_kernel(const float* __restrict__ doc, const float* __restrict__ q) {
    __shared__ float s[128 * 33];
    if (blockIdx.x < 2048) {
        int i = blockIdx.x * 256 + threadIdx.x;    // 524288 threads, 1 float4 each
        float4 v = reinterpret_cast<const float4*>(doc)[i];
        __half2 lo = __floats2half2_rn(v.x, v.y);
        __half2 hi = __floats2half2_rn(v.z, v.w);
        uint2 o;
        o.x = *reinterpret_cast<uint32_t*>(&lo);
        o.y = *reinterpret_cast<uint32_t*>(&hi);
        reinterpret_cast<uint2*>(g_doc)[i] = o;
    } else {
        // in[q][e][l] (e:128, l:32)  ->  g_qT[q][l][e]
        int qq = blockIdx.x - 2048;
        const float* src = q + qq * 4096;
        int tid = threadIdx.x;  // 256
        #pragma unroll
        for (int i = 0; i < 16; i++) {
            int idx = tid + i * 256;
            int e = idx >> 5, l = idx & 31;
            s[e * 33 + l] = src[idx];
        }
        __syncthreads();
        __half* dst = g_qT + qq * 4096;
        #pragma unroll
        for (int i = 0; i < 16; i++) {
            int idx = tid + i * 256;
            int l = idx >> 7, e = idx & 127;
            dst[idx] = __float2half_rn(s[e * 33 + l]);
        }
    }
}

// ---------------------------------------------------------------------------
// Primitives
// ---------------------------------------------------------------------------
__device__ __forceinline__ void mma16816_f16(uint32_t* c, const uint32_t* a, const uint32_t* b) {
    asm volatile(
        "mma.sync.aligned.m16n8k16.row.col.f16.f16.f16.f16 "
        "{%0,%1}, {%2,%3,%4,%5}, {%6,%7}, {%0,%1};\n"
        : "+r"(c[0]), "+r"(c[1])
        : "r"(a[0]), "r"(a[1]), "r"(a[2]), "r"(a[3]),
          "r"(b[0]), "r"(b[1]));
}

#define LDSM_X4(r0, r1, r2, r3, addr) \
    asm volatile("ldmatrix.sync.aligned.m8n8.x4.shared.b16 {%0,%1,%2,%3}, [%4];" \
                 : "=r"(r0), "=r"(r1), "=r"(r2), "=r"(r3) : "r"(addr))

__device__ __forceinline__ uint32_t smem_u32(const void* p) {
    uint32_t a;
    asm("{ .reg .u64 t; cvta.to.shared.u64 t, %1; cvt.u32.u64 %0, t; }" : "=r"(a) : "l"(p));
    return a;
}

#define CP16(saddr, gptr) \
    asm volatile("cp.async.cg.shared.global [%0], [%1], 16;" :: "r"(saddr), "l"(gptr))
#define CP_COMMIT() asm volatile("cp.async.commit_group;")
#define CP_WAIT(n)  asm volatile("cp.async.wait_group %0;" :: "n"(n))

// padded smem row: 136 f16 = 272 B (conflict-free LDSM, verified R4-R13)
#define ROWB 272
#define TILE_BYTES (128 * ROWB)                  // 34816
#define A_OFF(dd) ((dd) * TILE_BYTES)
#define B_OFF (2 * TILE_BYTES)
#define CM_OFF (3 * TILE_BYTES)                  // colmax [2][2][128] floats = 2048 B
#define SMEM_TOTAL (3 * TILE_BYTES + 2048)       // 106496 -> 2 CTAs/SM

// CTA: 256 threads = 8 warps in 2(doc) x 2(m) x 2(n); warp tile 64x64, f16 acc.
// Both docs computed concurrently by disjoint warp quads.  (R7 verbatim: 47.0 us)
__global__ void __launch_bounds__(256) maxsim_kernel(float* __restrict__ out) {
    extern __shared__ char smem[];
    float* colmax = reinterpret_cast<float*>(smem + CM_OFF);   // [doc][wm][128]

    const int dbase = blockIdx.x * 2;
    const int qg = blockIdx.y;
    const int tid = threadIdx.x;
    const int warp = tid >> 5;
    const int lane = tid & 31;
    const int wd = warp >> 2;         // doc within pair
    const int wm = (warp >> 1) & 1;   // m half
    const int wn = warp & 1;          // n half
    const int t4 = lane & 3;
    const int matid = lane >> 3;
    const int mrow = lane & 7;

    const uint32_t sbase = smem_u32(smem);

    // ---- async tile loads: q + both docs ----
    {
        const uint4* srcq  = reinterpret_cast<const uint4*>(g_qT + qg * 4 * LQ * EDIM);
        const uint4* srcd0 = reinterpret_cast<const uint4*>(g_doc + dbase * LD * EDIM);
        const uint4* srcd1 = reinterpret_cast<const uint4*>(g_doc + (dbase + 1) * LD * EDIM);
        #pragma unroll
        for (int i = 0; i < 8; i++) {
            int idx = tid + i * 256;                 // 0..2047
            int row = idx >> 4, col = idx & 15;
            uint32_t soff = (uint32_t)(row * 17 + col) * 16;
            CP16(sbase + B_OFF + soff, srcq + idx);
            CP16(sbase + A_OFF(0) + soff, srcd0 + idx);
            CP16(sbase + A_OFF(1) + soff, srcd1 + idx);
        }
        CP_COMMIT();
    }

    // LDSM per-lane offsets (verified mapping, 64x64 warp tile)
    uint32_t arow_off[4];
    #pragma unroll
    for (int mt = 0; mt < 4; mt++)
        arow_off[mt] = (uint32_t)((wm * 64 + mt * 16 + (matid & 1) * 8 + mrow) * ROWB
                                  + (matid >> 1) * 16);
    uint32_t brow_off[4];
    #pragma unroll
    for (int np = 0; np < 4; np++)
        brow_off[np] = (uint32_t)(B_OFF + (wn * 64 + np * 16 + (matid >> 1) * 8 + mrow) * ROWB
                                  + (matid & 1) * 16);

    CP_WAIT(0);
    __syncthreads();

    const uint32_t sA = sbase + A_OFF(wd);

    uint32_t acc[4][8][2];
    #pragma unroll
    for (int mt = 0; mt < 4; mt++)
        #pragma unroll
        for (int nt = 0; nt < 8; nt++) {
            acc[mt][nt][0] = 0u;
            acc[mt][nt][1] = 0u;
        }

    #pragma unroll
    for (int k0 = 0; k0 < EDIM; k0 += 16) {
        uint32_t a[4][4], b[8][2];
        #pragma unroll
        for (int mt = 0; mt < 4; mt++)
            LDSM_X4(a[mt][0], a[mt][1], a[mt][2], a[mt][3], sA + arow_off[mt] + k0 * 2);
        #pragma unroll
        for (int np = 0; np < 4; np++) {
            uint32_t t0, t1, t2, t3;
            LDSM_X4(t0, t1, t2, t3, sbase + brow_off[np] + k0 * 2);
            b[2 * np][0] = t0; b[2 * np][1] = t1;
            b[2 * np + 1][0] = t2; b[2 * np + 1][1] = t3;
        }
        #pragma unroll
        for (int mt = 0; mt < 4; mt++)
            #pragma unroll
            for (int nt = 0; nt < 8; nt++)
                mma16816_f16(acc[mt][nt], a[mt], b[nt]);
    }

    // ---- warp max over its 64 doc-token rows (packed f16x2 per col pair) ----
    #pragma unroll
    for (int nt = 0; nt < 8; nt++) {
        __half2 hm = __hmax2(*reinterpret_cast<__half2*>(&acc[0][nt][0]),
                             *reinterpret_cast<__half2*>(&acc[0][nt][1]));
        #pragma unroll
        for (int mt = 1; mt < 4; mt++) {
            hm = __hmax2(hm, *reinterpret_cast<__half2*>(&acc[mt][nt][0]));
            hm = __hmax2(hm, *reinterpret_cast<__half2*>(&acc[mt][nt][1]));
        }
        #pragma unroll
        for (int off = 4; off < 32; off <<= 1) {
            uint32_t u = __shfl_xor_sync(0xffffffffu, *reinterpret_cast<uint32_t*>(&hm), off);
            hm = __hmax2(hm, *reinterpret_cast<__half2*>(&u));
        }
        if (lane < 4) {   // lane == t4
            float2 f = __half22float2(hm);
            colmax[wd * 256 + wm * 128 + wn * 64 + nt * 8 + 2 * t4]     = f.x;
            colmax[wd * 256 + wm * 128 + wn * 64 + nt * 8 + 2 * t4 + 1] = f.y;
        }
    }
    __syncthreads();

    // ---- cross-warp max over t, then f32 sum over l per query ----
    {
        const int col = tid & 127;          // ql index within group; tid>>7 = doc
        const int dd = tid >> 7;
        float v = fmaxf(colmax[dd * 256 + col], colmax[dd * 256 + 128 + col]);
        #pragma unroll
        for (int off = 16; off; off >>= 1)
            v += __shfl_xor_sync(0xffffffffu, v, off);
        if (lane == 0)
            out[(qg * 4 + (col >> 5)) * ND + dbase + dd] = v;
    }
}

// ---------------------------------------------------------------------------
extern "C" void kernel_launch(void* const* d_in, const int* in_sizes, int n_in,
                              void* d_out, int out_size) {
    const float* doc   = (const float*)d_in[0];   // [128,128,128]
    const float* query = (const float*)d_in[1];   // [128,128,32]
    float* out = (float*)d_out;                   // [128,128]

    cudaFuncSetAttribute(maxsim_kernel, cudaFuncAttributeMaxDynamicSharedMemorySize, SMEM_TOTAL);

    conv_all_kernel<<<2176, 256>>>(doc, query);

    dim3 grid(ND / 2, LQ);   // 64 doc-pairs x 32 query groups
    maxsim_kernel<<<grid, 256, SMEM_TOTAL>>>(out);
}

// round 15
// speedup vs baseline: 1.5815x; 1.0354x over previous
#include <cuda_runtime.h>
#include <cuda_fp16.h>
#include <cstdint>

#define ND 128
#define NQ 128
#define LD 128
#define LQ 32
#define EDIM 128

#define NCTA 296           // persistent grid: exactly 2 waves of 148 SMs
#define NITEMS 2048        // 64 doc-pairs x 32 qgroups

// f16 staging (device globals: no allocation allowed)
__device__ __half g_doc[ND * LD * EDIM];      // [d][t][e]
__device__ __half g_qT[NQ * LQ * EDIM];       // [q][l][e]

// ---------------------------------------------------------------------------
// Merged conversion kernel: blocks [0,2048) convert doc, [2048,2176) convert q
// ---------------------------------------------------------------------------
__global__ void conv_all_kernel(const float* __restrict__ doc, const float* __restrict__ q) {
    __shared__ float s[128 * 33];
    if (blockIdx.x < 2048) {
        int i = blockIdx.x * 256 + threadIdx.x;    // 524288 threads, 1 float4 each
        float4 v = reinterpret_cast<const float4*>(doc)[i];
        __half2 lo = __floats2half2_rn(v.x, v.y);
        __half2 hi = __floats2half2_rn(v.z, v.w);
        uint2 o;
        o.x = *reinterpret_cast<uint32_t*>(&lo);
        o.y = *reinterpret_cast<uint32_t*>(&hi);
        reinterpret_cast<uint2*>(g_doc)[i] = o;
    } else {
        // in[q][e][l] (e:128, l:32)  ->  g_qT[q][l][e]
        int qq = blockIdx.x - 2048;
        const float* src = q + qq * 4096;
        int tid = threadIdx.x;  // 256
        #pragma unroll
        for (int i = 0; i < 16; i++) {
            int idx = tid + i * 256;
            int e = idx >> 5, l = idx & 31;
            s[e * 33 + l] = src[idx];
        }
        __syncthreads();
        __half* dst = g_qT + qq * 4096;
        #pragma unroll
        for (int i = 0; i < 16; i++) {
            int idx = tid + i * 256;
            int l = idx >> 7, e = idx & 127;
            dst[idx] = __float2half_rn(s[e * 33 + l]);
        }
    }
}

// ---------------------------------------------------------------------------
// Primitives
// ---------------------------------------------------------------------------
__device__ __forceinline__ void mma16816_f16(uint32_t* c, const uint32_t* a, const uint32_t* b) {
    asm volatile(
        "mma.sync.aligned.m16n8k16.row.col.f16.f16.f16.f16 "
        "{%0,%1}, {%2,%3,%4,%5}, {%6,%7}, {%0,%1};\n"
        : "+r"(c[0]), "+r"(c[1])
        : "r"(a[0]), "r"(a[1]), "r"(a[2]), "r"(a[3]),
          "r"(b[0]), "r"(b[1]));
}

#define LDSM_X4(r0, r1, r2, r3, addr) \
    asm volatile("ldmatrix.sync.aligned.m8n8.x4.shared.b16 {%0,%1,%2,%3}, [%4];" \
                 : "=r"(r0), "=r"(r1), "=r"(r2), "=r"(r3) : "r"(addr))

__device__ __forceinline__ uint32_t smem_u32(const void* p) {
    uint32_t a;
    asm("{ .reg .u64 t; cvta.to.shared.u64 t, %1; cvt.u32.u64 %0, t; }" : "=r"(a) : "l"(p));
    return a;
}

#define CP16(saddr, gptr) \
    asm volatile("cp.async.cg.shared.global [%0], [%1], 16;" :: "r"(saddr), "l"(gptr))
#define CP_COMMIT() asm volatile("cp.async.commit_group;")
#define CP_WAIT(n)  asm volatile("cp.async.wait_group %0;" :: "n"(n))

// padded smem row: 136 f16 = 272 B (conflict-free LDSM, verified R4-R14)
#define ROWB 272
#define TILE_BYTES (128 * ROWB)                  // 34816
#define A_OFF(dd) ((dd) * TILE_BYTES)
#define B_OFF (2 * TILE_BYTES)
#define CM_OFF (3 * TILE_BYTES)                  // colmax [2][2][128] floats = 2048 B
#define SMEM_TOTAL (3 * TILE_BYTES + 2048)       // 106496 -> 2 CTAs/SM

// Persistent CTA: 256 threads = 8 warps in 2(doc) x 2(m) x 2(n); warp tile 64x64,
// f16 acc (R7 inner machinery verbatim). Each CTA owns a contiguous run of items
// in qg-major order, reloading the q tile only on qgroup boundaries.
__global__ void __launch_bounds__(256) maxsim_kernel(float* __restrict__ out) {
    extern __shared__ char smem[];
    float* colmax = reinterpret_cast<float*>(smem + CM_OFF);   // [doc][wm][128]

    const int tid = threadIdx.x;
    const int warp = tid >> 5;
    const int lane = tid & 31;
    const int wd = warp >> 2;         // doc within pair
    const int wm = (warp >> 1) & 1;   // m half
    const int wn = warp & 1;          // n half
    const int t4 = lane & 3;
    const int matid = lane >> 3;
    const int mrow = lane & 7;

    const uint32_t sbase = smem_u32(smem);

    // LDSM per-lane offsets (verified mapping, 64x64 warp tile)
    uint32_t arow_off[4];
    #pragma unroll
    for (int mt = 0; mt < 4; mt++)
        arow_off[mt] = (uint32_t)((wm * 64 + mt * 16 + (matid & 1) * 8 + mrow) * ROWB
                                  + (matid >> 1) * 16);
    uint32_t brow_off[4];
    #pragma unroll
    for (int np = 0; np < 4; np++)
        brow_off[np] = (uint32_t)(B_OFF + (wn * 64 + np * 16 + (matid >> 1) * 8 + mrow) * ROWB
                                  + (matid & 1) * 16);

    // persistent item range (qg-major order: item = qg*64 + dpair)
    const int b = blockIdx.x;
    const int s_begin = (NITEMS * b) / NCTA;
    const int s_end = (NITEMS * (b + 1)) / NCTA;
    int prev_qg = -1;

    for (int s = s_begin; s < s_end; s++) {
        const int qg = s >> 6;
        const int dbase = (s & 63) * 2;

        // ---- async tile loads: q only on qgroup change, docs every item ----
        {
            const uint4* srcd0 = reinterpret_cast<const uint4*>(g_doc + dbase * LD * EDIM);
            const uint4* srcd1 = reinterpret_cast<const uint4*>(g_doc + (dbase + 1) * LD * EDIM);
            if (qg != prev_qg) {
                const uint4* srcq = reinterpret_cast<const uint4*>(g_qT + qg * 4 * LQ * EDIM);
                #pragma unroll
                for (int i = 0; i < 8; i++) {
                    int idx = tid + i * 256;             // 0..2047
                    int row = idx >> 4, col = idx & 15;
                    uint32_t soff = (uint32_t)(row * 17 + col) * 16;
                    CP16(sbase + B_OFF + soff, srcq + idx);
                    CP16(sbase + A_OFF(0) + soff, srcd0 + idx);
                    CP16(sbase + A_OFF(1) + soff, srcd1 + idx);
                }
            } else {
                #pragma unroll
                for (int i = 0; i < 8; i++) {
                    int idx = tid + i * 256;
                    int row = idx >> 4, col = idx & 15;
                    uint32_t soff = (uint32_t)(row * 17 + col) * 16;
                    CP16(sbase + A_OFF(0) + soff, srcd0 + idx);
                    CP16(sbase + A_OFF(1) + soff, srcd1 + idx);
                }
            }
            CP_COMMIT();
        }
        prev_qg = qg;

        CP_WAIT(0);
        __syncthreads();

        const uint32_t sA = sbase + A_OFF(wd);

        uint32_t acc[4][8][2];
        #pragma unroll
        for (int mt = 0; mt < 4; mt++)
            #pragma unroll
            for (int nt = 0; nt < 8; nt++) {
                acc[mt][nt][0] = 0u;
                acc[mt][nt][1] = 0u;
            }

        #pragma unroll
        for (int k0 = 0; k0 < EDIM; k0 += 16) {
            uint32_t a[4][4], bb[8][2];
            #pragma unroll
            for (int mt = 0; mt < 4; mt++)
                LDSM_X4(a[mt][0], a[mt][1], a[mt][2], a[mt][3], sA + arow_off[mt] + k0 * 2);
            #pragma unroll
            for (int np = 0; np < 4; np++) {
                uint32_t t0, t1, t2, t3;
                LDSM_X4(t0, t1, t2, t3, sbase + brow_off[np] + k0 * 2);
                bb[2 * np][0] = t0; bb[2 * np][1] = t1;
                bb[2 * np + 1][0] = t2; bb[2 * np + 1][1] = t3;
            }
            #pragma unroll
            for (int mt = 0; mt < 4; mt++)
                #pragma unroll
                for (int nt = 0; nt < 8; nt++)
                    mma16816_f16(acc[mt][nt], a[mt], bb[nt]);
        }

        // ---- warp max over its 64 doc-token rows (packed f16x2 per col pair) ----
        #pragma unroll
        for (int nt = 0; nt < 8; nt++) {
            __half2 hm = __hmax2(*reinterpret_cast<__half2*>(&acc[0][nt][0]),
                                 *reinterpret_cast<__half2*>(&acc[0][nt][1]));
            #pragma unroll
            for (int mt = 1; mt < 4; mt++) {
                hm = __hmax2(hm, *reinterpret_cast<__half2*>(&acc[mt][nt][0]));
                hm = __hmax2(hm, *reinterpret_cast<__half2*>(&acc[mt][nt][1]));
            }
            #pragma unroll
            for (int off = 4; off < 32; off <<= 1) {
                uint32_t u = __shfl_xor_sync(0xffffffffu, *reinterpret_cast<uint32_t*>(&hm), off);
                hm = __hmax2(hm, *reinterpret_cast<__half2*>(&u));
            }
            if (lane < 4) {   // lane == t4
                float2 f = __half22float2(hm);
                colmax[wd * 256 + wm * 128 + wn * 64 + nt * 8 + 2 * t4]     = f.x;
                colmax[wd * 256 + wm * 128 + wn * 64 + nt * 8 + 2 * t4 + 1] = f.y;
            }
        }
        __syncthreads();

        // ---- cross-warp max over t, then f32 sum over l per query ----
        {
            const int col = tid & 127;          // ql index within group; tid>>7 = doc
            const int dd = tid >> 7;
            float v = fmaxf(colmax[dd * 256 + col], colmax[dd * 256 + 128 + col]);
            #pragma unroll
            for (int off = 16; off; off >>= 1)
                v += __shfl_xor_sync(0xffffffffu, v, off);
            if (lane == 0)
                out[(qg * 4 + (col >> 5)) * ND + dbase + dd] = v;
        }
        __syncthreads();   // colmax + doc buffers reusable next item
    }
}

// ---------------------------------------------------------------------------
extern "C" void kernel_launch(void* const* d_in, const int* in_sizes, int n_in,
                              void* d_out, int out_size) {
    const float* doc   = (const float*)d_in[0];   // [128,128,128]
    const float* query = (const float*)d_in[1];   // [128,128,32]
    float* out = (float*)d_out;                   // [128,128]

    cudaFuncSetAttribute(maxsim_kernel, cudaFuncAttributeMaxDynamicSharedMemorySize, SMEM_TOTAL);

    conv_all_kernel<<<2176, 256>>>(doc, query);

    maxsim_kernel<<<NCTA, 256, SMEM_TOTAL>>>(out);
}